// round 15
// baseline (speedup 1.0000x reference)
#include <cuda_runtime.h>
#include <cuda_fp16.h>
#include <cstdint>

#define NN 50000
#define NE 800000
#define NM (NE + NN)
#define HD 256
#define EPSV 1e-5f

// ==================== PTX helpers ====================
#define LDSM4(r, addr) asm volatile( \
    "ldmatrix.sync.aligned.m8n8.x4.shared.b16 {%0,%1,%2,%3}, [%4];" \
    : "=r"((r)[0]), "=r"((r)[1]), "=r"((r)[2]), "=r"((r)[3]) : "r"(addr))

#define MMA_FP16(d, a, b0, b1) asm volatile( \
    "mma.sync.aligned.m16n8k16.row.col.f32.f16.f16.f32 " \
    "{%0,%1,%2,%3}, {%4,%5,%6,%7}, {%8,%9}, {%0,%1,%2,%3};" \
    : "+f"((d)[0]), "+f"((d)[1]), "+f"((d)[2]), "+f"((d)[3]) \
    : "r"((a)[0]), "r"((a)[1]), "r"((a)[2]), "r"((a)[3]), "r"(b0), "r"(b1))

#define CP_ASYNC16(dst, src) \
    asm volatile("cp.async.cg.shared.global [%0], [%1], 16;" :: "r"(dst), "l"(src))
#define CP_COMMIT() asm volatile("cp.async.commit_group;" ::: "memory")
#define CP_WAIT1() asm volatile("cp.async.wait_group 1;" ::: "memory")
#define CP_WAIT0() asm volatile("cp.async.wait_group 0;" ::: "memory")

__device__ __forceinline__ uint32_t smem_to_u32(const void* smem_ptr) {
    uint32_t addr;
    asm("{ .reg .u64 tmp; cvta.to.shared.u64 tmp, %1; cvt.u32.u64 %0, tmp; }"
        : "=r"(addr) : "l"(smem_ptr));
    return addr;
}

// ==================== device scratch ====================
__device__ __align__(256) __half g_xw[(size_t)NN * HD];
__device__ __align__(256) __half g_af[(size_t)NN * HD];
__device__ __align__(256) __half g_w1t[256 * 128];
__device__ __align__(256) __half g_w2t[256 * 256];
__device__ __align__(256) __half g_w3t[256 * 256];
__device__ __align__(256) __half g_wf1t[128 * 256];
__device__ __align__(16) int   g_cnt[NN];
__device__ __align__(16) int   g_off[NN + 4];
__device__ int   g_slot[NE];          // per-edge slot within its target row
__device__ int   g_src[NM];
__device__ float g_nrm[NM];
__device__ int   g_is64;

__device__ __forceinline__ int edge_val(const void* ei, int which, int e) {
    if (g_is64) return (int)((const long long*)ei)[(size_t)which * NE + e];
    return ((const int*)ei)[(size_t)which * NE + e];
}

// ==== main-stream prologue: x->fp16 + weight transpose+fp16 ====
__global__ void k_cvtw(
    const float* __restrict__ x,
    const float* __restrict__ W1, const float* __restrict__ W2,
    const float* __restrict__ W3, const float* __restrict__ Wf1,
    __half* __restrict__ Af,
    __half* __restrict__ w1t, __half* __restrict__ w2t,
    __half* __restrict__ w3t, __half* __restrict__ wft)
{
    int idx = blockIdx.x * blockDim.x + threadIdx.x;
    if (idx < NN * 128) Af[idx] = __float2half_rn(x[idx]);
    if (idx < 196608) {
        const float* W; __half* T; int K, Nc, local;
        if (idx < 32768)       { W = W1;  T = w1t; K = 128; Nc = 256; local = idx; }
        else if (idx < 98304)  { W = W2;  T = w2t; K = 256; Nc = 256; local = idx - 32768; }
        else if (idx < 163840) { W = W3;  T = w3t; K = 256; Nc = 256; local = idx - 98304; }
        else                   { W = Wf1; T = wft; K = 256; Nc = 128; local = idx - 163840; }
        int k = local / Nc, n = local % Nc;
        T[(size_t)n * K + k] = __float2half_rn(W[local]);
    }
}

// ==== side-stream: cnt init + edge dtype detect ====
__global__ void k_init(const int* __restrict__ eip) {
    int idx = blockIdx.x * blockDim.x + threadIdx.x;
    if (idx < NN) g_cnt[idx] = 1;     // self-loop occupies slot 0
    if (blockIdx.x == 0 && threadIdx.x < 32) {
        int lane = threadIdx.x;
        int nz = 0;
        for (int j = lane; j < 1024; j += 32) nz |= eip[2 * j + 1];
        unsigned any = __ballot_sync(0xffffffffu, nz != 0);
        if (lane == 0) g_is64 = (any == 0) ? 1 : 0;
    }
}

// ==== degree histogram; atomic return value IS the edge's row-local slot ====
__global__ void k_deg(const void* __restrict__ ei) {
    int e = blockIdx.x * blockDim.x + threadIdx.x;
    if (e < NE) {
        int c = edge_val(ei, 1, e);
        g_slot[e] = atomicAdd(&g_cnt[c], 1);   // >=1 (0 = self-loop)
    }
}

// ===== single-block scan: ALL tiles prefetched to regs, shuffle+carry =====
__global__ void k_scan() {
    __shared__ int warp_sums[32];
    __shared__ int s_carry;
    constexpr int nInt4 = NN / 4;
    constexpr int NT = (nInt4 + 1023) / 1024;
    int tid = threadIdx.x;
    int lane = tid & 31, wid = tid >> 5;
    const int4* cnt4 = (const int4*)g_cnt;
    int4* off4 = (int4*)g_off;

    int4 v[NT];
#pragma unroll
    for (int t = 0; t < NT; t++) {
        int i = t * 1024 + tid;
        v[t] = (i < nInt4) ? cnt4[i] : make_int4(0, 0, 0, 0);
    }
    if (tid == 0) s_carry = 0;
    __syncthreads();

#pragma unroll
    for (int t = 0; t < NT; t++) {
        int i = t * 1024 + tid;
        int s01 = v[t].x + v[t].y;
        int tsum = s01 + v[t].z + v[t].w;
        int incl = tsum;
#pragma unroll
        for (int o = 1; o < 32; o <<= 1) {
            int u = __shfl_up_sync(0xffffffffu, incl, o);
            if (lane >= o) incl += u;
        }
        if (lane == 31) warp_sums[wid] = incl;
        __syncthreads();
        if (wid == 0) {
            int ws = warp_sums[lane];
#pragma unroll
            for (int o = 1; o < 32; o <<= 1) {
                int u = __shfl_up_sync(0xffffffffu, ws, o);
                if (lane >= o) ws += u;
            }
            warp_sums[lane] = ws;
        }
        __syncthreads();
        int excl = incl - tsum + (wid > 0 ? warp_sums[wid - 1] : 0) + s_carry;
        if (i < nInt4) {
            int4 o4;
            o4.x = excl;
            o4.y = excl + v[t].x;
            o4.z = excl + s01;
            o4.w = excl + s01 + v[t].z;
            off4[i] = o4;
        }
        __syncthreads();
        if (tid == 0) s_carry += warp_sums[31];
        __syncthreads();
    }
    if (tid == 0) g_off[NN] = s_carry;
}

// ====== self-loops + edge fill: NO atomics (slot precomputed in k_deg) ======
__global__ void k_fillself(const void* __restrict__ ei) {
    int t = blockIdx.x * blockDim.x + threadIdx.x;
    if (t < NN) {
        int o = g_off[t];
        g_src[o] = t;
        g_nrm[o] = 1.0f / (float)g_cnt[t];
    } else if (t < NN + NE) {
        int e = t - NN;
        int r = edge_val(ei, 0, e);
        int c = edge_val(ei, 1, e);
        int s = g_off[c] + g_slot[e];
        g_src[s] = r;
        g_nrm[s] = rsqrtf((float)g_cnt[r]) * rsqrtf((float)g_cnt[c]);
    }
}

// ============== fp16 GEMM: 32x64 warp tile, 3-stage, 2 CTAs/SM ==========
template<int K>
__global__ __launch_bounds__(256, 2) void k_mma(
    const __half* __restrict__ Af, const __half* __restrict__ Bt,
    __half* __restrict__ C, int M, int Nc)
{
    constexpr int BK = 32;
    constexpr int NC_CHUNK = K / BK;
    constexpr int SA = BK + 8;
    constexpr int QTR = 128 * SA * 2;
    constexpr int STAGE = 2 * QTR;

    extern __shared__ char smem[];
    uint32_t smem_base = smem_to_u32(smem);
    int tid = threadIdx.x;
    int lane = tid & 31;
    int wid = tid >> 5;
    int bm = blockIdx.y * 128;
    int bn = blockIdx.x * 128;
    int wm = (wid >> 1) * 32;
    int wn = (wid & 1) * 64;
    int lt = lane >> 3;
    int lr = lane & 7;

    uint32_t a_base[2];
#pragma unroll
    for (int mi = 0; mi < 2; mi++)
        a_base[mi] = smem_base +
            ((wm + mi * 16 + (lt & 1) * 8 + lr) * SA + (lt >> 1) * 8) * 2;
    uint32_t b_base[4];
#pragma unroll
    for (int nj = 0; nj < 4; nj++)
        b_base[nj] = smem_base + QTR +
            ((wn + nj * 16 + (lt >> 1) * 8 + lr) * SA + (lt & 1) * 8) * 2;

    auto issue_chunk = [&](int c) {
        uint32_t dst = smem_base + (uint32_t)(c % 3) * STAGE;
#pragma unroll
        for (int t = 0; t < 4; t++) {
            int i = tid + t * 256;
            if (i < 512) {
                int m = i >> 2, k = (i & 3) * 8;
                int gm = bm + m;
                if (gm > M - 1) gm = M - 1;
                CP_ASYNC16(dst + (m * SA + k) * 2,
                           Af + (size_t)gm * K + c * BK + k);
            } else {
                int j = i - 512;
                int n = j >> 2, k = (j & 3) * 8;
                CP_ASYNC16(dst + QTR + (n * SA + k) * 2,
                           Bt + (size_t)(bn + n) * K + c * BK + k);
            }
        }
    };

    float acc[2][8][4];
#pragma unroll
    for (int mi = 0; mi < 2; mi++)
#pragma unroll
        for (int ni = 0; ni < 8; ni++)
#pragma unroll
            for (int v = 0; v < 4; v++) acc[mi][ni][v] = 0.f;

    issue_chunk(0); CP_COMMIT();
    if (NC_CHUNK > 1) { issue_chunk(1); CP_COMMIT(); }

    for (int c = 0; c < NC_CHUNK; c++) {
        if (c + 1 < NC_CHUNK) CP_WAIT1(); else CP_WAIT0();
        __syncthreads();
        if (c + 2 < NC_CHUNK) { issue_chunk(c + 2); CP_COMMIT(); }

        uint32_t sbuf = (uint32_t)(c % 3) * STAGE;
#pragma unroll
        for (int ks = 0; ks < BK / 16; ks++) {
            uint32_t o = sbuf + ks * 32;
            uint32_t af[2][4];
            LDSM4(af[0], a_base[0] + o);
            LDSM4(af[1], a_base[1] + o);
            uint32_t bB[2][4];
            LDSM4(bB[0], b_base[0] + o);
#pragma unroll
            for (int nj = 0; nj < 4; nj++) {
                int cur = nj & 1, nxt = cur ^ 1;
                if (nj < 3) LDSM4(bB[nxt], b_base[nj + 1] + o);
                MMA_FP16(acc[0][2 * nj],     af[0], bB[cur][0], bB[cur][1]);
                MMA_FP16(acc[1][2 * nj],     af[1], bB[cur][0], bB[cur][1]);
                MMA_FP16(acc[0][2 * nj + 1], af[0], bB[cur][2], bB[cur][3]);
                MMA_FP16(acc[1][2 * nj + 1], af[1], bB[cur][2], bB[cur][3]);
            }
        }
    }

    int g = lane >> 2, tg = lane & 3;
#pragma unroll
    for (int mi = 0; mi < 2; mi++) {
        int r0 = bm + wm + mi * 16 + g;
#pragma unroll
        for (int ni = 0; ni < 8; ni++) {
            int col = bn + wn + ni * 8 + tg * 2;
            __half2 v0 = __floats2half2_rn(acc[mi][ni][0], acc[mi][ni][1]);
            __half2 v1 = __floats2half2_rn(acc[mi][ni][2], acc[mi][ni][3]);
            if (r0 < M)     *(__half2*)(C + (size_t)r0 * Nc + col) = v0;
            if (r0 + 8 < M) *(__half2*)(C + (size_t)(r0 + 8) * Nc + col) = v1;
        }
    }
}

// ======== head GEMM with fused relu + Wf2 reduction ========
__global__ __launch_bounds__(256, 2) void k_head(
    const __half* __restrict__ Af, const __half* __restrict__ Bt,
    const float* __restrict__ bias, int M,
    const float* __restrict__ wf2, const float* __restrict__ bf2,
    float* __restrict__ outp)
{
    constexpr int K = 256;
    constexpr int BK = 32;
    constexpr int NC_CHUNK = K / BK;
    constexpr int SA = BK + 8;
    constexpr int QTR = 128 * SA * 2;
    constexpr int STAGE = 2 * QTR;

    extern __shared__ char smem[];
    __shared__ float red[128];
    uint32_t smem_base = smem_to_u32(smem);
    int tid = threadIdx.x;
    int lane = tid & 31;
    int wid = tid >> 5;
    int bm = blockIdx.x * 128;
    int wm = (wid >> 1) * 32;
    int wn = (wid & 1) * 64;
    int lt = lane >> 3;
    int lr = lane & 7;

    if (tid < 128) red[tid] = 0.f;

    uint32_t a_base[2];
#pragma unroll
    for (int mi = 0; mi < 2; mi++)
        a_base[mi] = smem_base +
            ((wm + mi * 16 + (lt & 1) * 8 + lr) * SA + (lt >> 1) * 8) * 2;
    uint32_t b_base[4];
#pragma unroll
    for (int nj = 0; nj < 4; nj++)
        b_base[nj] = smem_base + QTR +
            ((wn + nj * 16 + (lt >> 1) * 8 + lr) * SA + (lt & 1) * 8) * 2;

    auto issue_chunk = [&](int c) {
        uint32_t dst = smem_base + (uint32_t)(c % 3) * STAGE;
#pragma unroll
        for (int t = 0; t < 4; t++) {
            int i = tid + t * 256;
            if (i < 512) {
                int m = i >> 2, k = (i & 3) * 8;
                int gm = bm + m;
                if (gm > M - 1) gm = M - 1;
                CP_ASYNC16(dst + (m * SA + k) * 2,
                           Af + (size_t)gm * K + c * BK + k);
            } else {
                int j = i - 512;
                int n = j >> 2, k = (j & 3) * 8;
                CP_ASYNC16(dst + QTR + (n * SA + k) * 2,
                           Bt + (size_t)n * K + c * BK + k);
            }
        }
    };

    float acc[2][8][4];
#pragma unroll
    for (int mi = 0; mi < 2; mi++)
#pragma unroll
        for (int ni = 0; ni < 8; ni++)
#pragma unroll
            for (int v = 0; v < 4; v++) acc[mi][ni][v] = 0.f;

    issue_chunk(0); CP_COMMIT();
    issue_chunk(1); CP_COMMIT();

    for (int c = 0; c < NC_CHUNK; c++) {
        if (c + 1 < NC_CHUNK) CP_WAIT1(); else CP_WAIT0();
        __syncthreads();
        if (c + 2 < NC_CHUNK) { issue_chunk(c + 2); CP_COMMIT(); }

        uint32_t sbuf = (uint32_t)(c % 3) * STAGE;
#pragma unroll
        for (int ks = 0; ks < BK / 16; ks++) {
            uint32_t o = sbuf + ks * 32;
            uint32_t af[2][4];
            LDSM4(af[0], a_base[0] + o);
            LDSM4(af[1], a_base[1] + o);
            uint32_t bB[2][4];
            LDSM4(bB[0], b_base[0] + o);
#pragma unroll
            for (int nj = 0; nj < 4; nj++) {
                int cur = nj & 1, nxt = cur ^ 1;
                if (nj < 3) LDSM4(bB[nxt], b_base[nj + 1] + o);
                MMA_FP16(acc[0][2 * nj],     af[0], bB[cur][0], bB[cur][1]);
                MMA_FP16(acc[1][2 * nj],     af[1], bB[cur][0], bB[cur][1]);
                MMA_FP16(acc[0][2 * nj + 1], af[0], bB[cur][2], bB[cur][3]);
                MMA_FP16(acc[1][2 * nj + 1], af[1], bB[cur][2], bB[cur][3]);
            }
        }
    }

    int g = lane >> 2, tg = lane & 3;
    __syncthreads();
#pragma unroll
    for (int mi = 0; mi < 2; mi++) {
        float p0 = 0.f, p1 = 0.f;
#pragma unroll
        for (int ni = 0; ni < 8; ni++) {
            int col = wn + ni * 8 + tg * 2;
            float bx = bias[col], by = bias[col + 1];
            float w0 = wf2[col], w1 = wf2[col + 1];
            p0 += fmaxf(acc[mi][ni][0] + bx, 0.f) * w0
                + fmaxf(acc[mi][ni][1] + by, 0.f) * w1;
            p1 += fmaxf(acc[mi][ni][2] + bx, 0.f) * w0
                + fmaxf(acc[mi][ni][3] + by, 0.f) * w1;
        }
        atomicAdd(&red[wm + mi * 16 + g], p0);
        atomicAdd(&red[wm + mi * 16 + 8 + g], p1);
    }
    __syncthreads();
    if (tid < 128) {
        int r = bm + tid;
        if (r < M) outp[r] = red[tid] + bf2[0];
    }
}

// ======== fused aggregate(+bias)+LN+ReLU+residual, fp16 gather ========
template<int MODE>
__global__ __launch_bounds__(256) void k_agg(
    const __half* __restrict__ xw, const float* __restrict__ bias,
    const float* __restrict__ gam, const float* __restrict__ bet,
    const __half* __restrict__ prev, __half* __restrict__ outp)
{
    int n = (blockIdx.x * blockDim.x + threadIdx.x) >> 5;
    int lane = threadIdx.x & 31;
    if (n >= NN) return;
    int s0 = g_off[n], s1 = g_off[n + 1];
    float a[8] = {0.f, 0.f, 0.f, 0.f, 0.f, 0.f, 0.f, 0.f};
    int s = s0;

    auto accum = [&](uint4 raw, float w) {
        union { uint4 u; __half2 h[4]; } cv;
        cv.u = raw;
#pragma unroll
        for (int q = 0; q < 4; q++) {
            float2 f = __half22float2(cv.h[q]);
            a[2 * q]     += w * f.x;
            a[2 * q + 1] += w * f.y;
        }
    };

    for (; s + 3 < s1; s += 4) {
        int i0 = g_src[s], i1 = g_src[s + 1], i2 = g_src[s + 2], i3 = g_src[s + 3];
        float w0 = g_nrm[s], w1 = g_nrm[s + 1], w2 = g_nrm[s + 2], w3 = g_nrm[s + 3];
        uint4 r0 = ((const uint4*)(xw + (size_t)i0 * HD))[lane];
        uint4 r1 = ((const uint4*)(xw + (size_t)i1 * HD))[lane];
        uint4 r2 = ((const uint4*)(xw + (size_t)i2 * HD))[lane];
        uint4 r3 = ((const uint4*)(xw + (size_t)i3 * HD))[lane];
        accum(r0, w0); accum(r1, w1); accum(r2, w2); accum(r3, w3);
    }
    for (; s < s1; s++) {
        uint4 r0 = ((const uint4*)(xw + (size_t)g_src[s] * HD))[lane];
        accum(r0, g_nrm[s]);
    }

    const float4* bp = (const float4*)bias + (lane << 1);
    float4 b0 = bp[0], b1 = bp[1];
    a[0] += b0.x; a[1] += b0.y; a[2] += b0.z; a[3] += b0.w;
    a[4] += b1.x; a[5] += b1.y; a[6] += b1.z; a[7] += b1.w;

    float sm = 0.f, sq = 0.f;
#pragma unroll
    for (int i = 0; i < 8; i++) { sm += a[i]; sq += a[i] * a[i]; }
#pragma unroll
    for (int o = 16; o > 0; o >>= 1) {
        sm += __shfl_xor_sync(0xffffffffu, sm, o);
        sq += __shfl_xor_sync(0xffffffffu, sq, o);
    }
    float mu = sm * (1.f / HD);
    float inv = rsqrtf(sq * (1.f / HD) - mu * mu + EPSV);

    const float4* gp = (const float4*)gam + (lane << 1);
    const float4* ep = (const float4*)bet + (lane << 1);
    float4 gg0 = gp[0], gg1 = gp[1], ee0 = ep[0], ee1 = ep[1];
    float gv[8] = { gg0.x, gg0.y, gg0.z, gg0.w, gg1.x, gg1.y, gg1.z, gg1.w };
    float ev[8] = { ee0.x, ee0.y, ee0.z, ee0.w, ee1.x, ee1.y, ee1.z, ee1.w };
    float r[8];
#pragma unroll
    for (int i = 0; i < 8; i++)
        r[i] = fmaxf((a[i] - mu) * inv * gv[i] + ev[i], 0.f);

    size_t obase = (size_t)n * HD + lane * 8;
    if (MODE == 2 || MODE == 3) {
        union { uint4 u; __half h[8]; } pu;
        pu.u = *(const uint4*)(prev + obase);
#pragma unroll
        for (int i = 0; i < 8; i++) {
            float pv = __half2float(pu.h[i]);
            r[i] = (MODE == 2) ? (r[i] + 0.7f * pv) : (r[i] * 0.7f + pv);
        }
    }

    union { __half h[8]; uint4 u; } uo;
#pragma unroll
    for (int i = 0; i < 8; i++) uo.h[i] = __float2half_rn(r[i]);
    *(uint4*)(outp + obase) = uo.u;
}

// ==================== orchestration ====================
extern "C" void kernel_launch(void* const* d_in, const int* in_sizes, int n_in,
                              void* d_out, int out_size)
{
    const float* x   = (const float*)d_in[0];
    const void*  ei  = d_in[1];
    const float* W1  = (const float*)d_in[2];
    const float* b1  = (const float*)d_in[3];
    const float* g1  = (const float*)d_in[4];
    const float* be1 = (const float*)d_in[5];
    const float* W2  = (const float*)d_in[6];
    const float* b2  = (const float*)d_in[7];
    const float* g2  = (const float*)d_in[8];
    const float* be2 = (const float*)d_in[9];
    const float* W3  = (const float*)d_in[10];
    const float* b3  = (const float*)d_in[11];
    const float* g3  = (const float*)d_in[12];
    const float* be3 = (const float*)d_in[13];
    const float* Wf1 = (const float*)d_in[14];
    const float* bf1 = (const float*)d_in[15];
    const float* Wf2 = (const float*)d_in[16];
    const float* bf2 = (const float*)d_in[17];
    float* out = (float*)d_out;

    __half *xw_p, *af, *w1t, *w2t, *w3t, *wft;
    cudaGetSymbolAddress((void**)&xw_p, g_xw);
    cudaGetSymbolAddress((void**)&af, g_af);
    cudaGetSymbolAddress((void**)&w1t, g_w1t);
    cudaGetSymbolAddress((void**)&w2t, g_w2t);
    cudaGetSymbolAddress((void**)&w3t, g_w3t);
    cudaGetSymbolAddress((void**)&wft, g_wf1t);

    const int SMEM = 3 * 20480;
    cudaFuncSetAttribute(k_mma<128>, cudaFuncAttributeMaxDynamicSharedMemorySize, SMEM);
    cudaFuncSetAttribute(k_mma<256>, cudaFuncAttributeMaxDynamicSharedMemorySize, SMEM);
    cudaFuncSetAttribute(k_head,     cudaFuncAttributeMaxDynamicSharedMemorySize, SMEM);

    static cudaStream_t s2 = nullptr;
    static cudaEvent_t evFork = nullptr, evJoin = nullptr;
    if (s2 == nullptr) {
        cudaStreamCreateWithFlags(&s2, cudaStreamNonBlocking);
        cudaEventCreateWithFlags(&evFork, cudaEventDisableTiming);
        cudaEventCreateWithFlags(&evJoin, cudaEventDisableTiming);
    }

    const int TB = 256;
    int gWarp = (NN * 32 + TB - 1) / TB;
    int mBlocks = (NN + 127) / 128;

    // ---- fork: side stream builds CSR while main stream does cvt + GEMM1 ----
    cudaEventRecord(evFork, 0);
    cudaStreamWaitEvent(s2, evFork, 0);

    // side stream: init+detect -> deg(+slot) -> scan -> fill(no atomics)
    k_init<<<(NN + TB - 1) / TB, TB, 0, s2>>>((const int*)ei);
    k_deg<<<(NE + TB - 1) / TB, TB, 0, s2>>>(ei);
    k_scan<<<1, 1024, 0, s2>>>();
    k_fillself<<<(NN + NE + TB - 1) / TB, TB, 0, s2>>>(ei);
    cudaEventRecord(evJoin, s2);

    // main stream: x/weights convert -> layer-1 GEMM
    k_cvtw<<<(NN * 128 + TB - 1) / TB, TB>>>(x, W1, W2, W3, Wf1,
                                             af, w1t, w2t, w3t, wft);
    k_mma<128><<<dim3(2, mBlocks), 256, SMEM>>>(af, w1t, xw_p, NN, 256);

    // join
    cudaStreamWaitEvent(0, evJoin, 0);

    k_agg<1><<<gWarp, TB>>>(xw_p, b1, g1, be1, nullptr, af);

    k_mma<256><<<dim3(2, mBlocks), 256, SMEM>>>(af, w2t, xw_p, NN, 256);
    k_agg<2><<<gWarp, TB>>>(xw_p, b2, g2, be2, af, af);

    k_mma<256><<<dim3(2, mBlocks), 256, SMEM>>>(af, w3t, xw_p, NN, 256);
    k_agg<3><<<gWarp, TB>>>(xw_p, b3, g3, be3, af, af);

    k_head<<<mBlocks, 256, SMEM>>>(af, wft, bf1, NN, Wf2, bf2, out);
}

// round 16
// speedup vs baseline: 1.0195x; 1.0195x over previous
#include <cuda_runtime.h>
#include <cuda_fp16.h>
#include <cstdint>

#define NN 50000
#define NE 800000
#define NM (NE + NN)
#define HD 256
#define EPSV 1e-5f

// ==================== PTX helpers ====================
#define LDSM4(r, addr) asm volatile( \
    "ldmatrix.sync.aligned.m8n8.x4.shared.b16 {%0,%1,%2,%3}, [%4];" \
    : "=r"((r)[0]), "=r"((r)[1]), "=r"((r)[2]), "=r"((r)[3]) : "r"(addr))

#define MMA_FP16(d, a, b0, b1) asm volatile( \
    "mma.sync.aligned.m16n8k16.row.col.f32.f16.f16.f32 " \
    "{%0,%1,%2,%3}, {%4,%5,%6,%7}, {%8,%9}, {%0,%1,%2,%3};" \
    : "+f"((d)[0]), "+f"((d)[1]), "+f"((d)[2]), "+f"((d)[3]) \
    : "r"((a)[0]), "r"((a)[1]), "r"((a)[2]), "r"((a)[3]), "r"(b0), "r"(b1))

#define CP_ASYNC16(dst, src) \
    asm volatile("cp.async.cg.shared.global [%0], [%1], 16;" :: "r"(dst), "l"(src))
#define CP_COMMIT() asm volatile("cp.async.commit_group;" ::: "memory")
#define CP_WAIT1() asm volatile("cp.async.wait_group 1;" ::: "memory")
#define CP_WAIT0() asm volatile("cp.async.wait_group 0;" ::: "memory")

__device__ __forceinline__ uint32_t smem_to_u32(const void* smem_ptr) {
    uint32_t addr;
    asm("{ .reg .u64 tmp; cvta.to.shared.u64 tmp, %1; cvt.u32.u64 %0, tmp; }"
        : "=r"(addr) : "l"(smem_ptr));
    return addr;
}

// ==================== device scratch ====================
__device__ __align__(256) __half g_xw[(size_t)NN * HD];
__device__ __align__(256) __half g_af[(size_t)NN * HD];
__device__ __align__(256) __half g_w1t[256 * 128];
__device__ __align__(256) __half g_w2t[256 * 256];
__device__ __align__(256) __half g_w3t[256 * 256];
__device__ __align__(256) __half g_wf1t[128 * 256];
__device__ __align__(16) int  g_cnt[NN];
__device__ __align__(16) int  g_off[NN + 4];
__device__ int  g_slot[NE];           // per-edge slot within its target row
__device__ __align__(16) int2 g_ed[NM];  // packed (src, nrm-bits) per CSR entry
__device__ int  g_is64;

__device__ __forceinline__ int edge_val(const void* ei, int which, int e) {
    if (g_is64) return (int)((const long long*)ei)[(size_t)which * NE + e];
    return ((const int*)ei)[(size_t)which * NE + e];
}

// ==== main-stream prologue: x->fp16 + weight transpose+fp16 ====
__global__ void k_cvtw(
    const float* __restrict__ x,
    const float* __restrict__ W1, const float* __restrict__ W2,
    const float* __restrict__ W3, const float* __restrict__ Wf1,
    __half* __restrict__ Af,
    __half* __restrict__ w1t, __half* __restrict__ w2t,
    __half* __restrict__ w3t, __half* __restrict__ wft)
{
    int idx = blockIdx.x * blockDim.x + threadIdx.x;
    if (idx < NN * 128) Af[idx] = __float2half_rn(x[idx]);
    if (idx < 196608) {
        const float* W; __half* T; int K, Nc, local;
        if (idx < 32768)       { W = W1;  T = w1t; K = 128; Nc = 256; local = idx; }
        else if (idx < 98304)  { W = W2;  T = w2t; K = 256; Nc = 256; local = idx - 32768; }
        else if (idx < 163840) { W = W3;  T = w3t; K = 256; Nc = 256; local = idx - 98304; }
        else                   { W = Wf1; T = wft; K = 256; Nc = 128; local = idx - 163840; }
        int k = local / Nc, n = local % Nc;
        T[(size_t)n * K + k] = __float2half_rn(W[local]);
    }
}

// ==== side-stream: cnt init + edge dtype detect ====
__global__ void k_init(const int* __restrict__ eip) {
    int idx = blockIdx.x * blockDim.x + threadIdx.x;
    if (idx < NN) g_cnt[idx] = 1;     // self-loop occupies slot 0
    if (blockIdx.x == 0 && threadIdx.x < 32) {
        int lane = threadIdx.x;
        int nz = 0;
        for (int j = lane; j < 1024; j += 32) nz |= eip[2 * j + 1];
        unsigned any = __ballot_sync(0xffffffffu, nz != 0);
        if (lane == 0) g_is64 = (any == 0) ? 1 : 0;
    }
}

// ==== degree histogram; atomic return value IS the edge's row-local slot ====
__global__ void k_deg(const void* __restrict__ ei) {
    int e = blockIdx.x * blockDim.x + threadIdx.x;
    if (e < NE) {
        int c = edge_val(ei, 1, e);
        g_slot[e] = atomicAdd(&g_cnt[c], 1);
    }
}

// ===== single-block scan: ALL tiles prefetched to regs, shuffle+carry =====
__global__ void k_scan() {
    __shared__ int warp_sums[32];
    __shared__ int s_carry;
    constexpr int nInt4 = NN / 4;
    constexpr int NT = (nInt4 + 1023) / 1024;
    int tid = threadIdx.x;
    int lane = tid & 31, wid = tid >> 5;
    const int4* cnt4 = (const int4*)g_cnt;
    int4* off4 = (int4*)g_off;

    int4 v[NT];
#pragma unroll
    for (int t = 0; t < NT; t++) {
        int i = t * 1024 + tid;
        v[t] = (i < nInt4) ? cnt4[i] : make_int4(0, 0, 0, 0);
    }
    if (tid == 0) s_carry = 0;
    __syncthreads();

#pragma unroll
    for (int t = 0; t < NT; t++) {
        int i = t * 1024 + tid;
        int s01 = v[t].x + v[t].y;
        int tsum = s01 + v[t].z + v[t].w;
        int incl = tsum;
#pragma unroll
        for (int o = 1; o < 32; o <<= 1) {
            int u = __shfl_up_sync(0xffffffffu, incl, o);
            if (lane >= o) incl += u;
        }
        if (lane == 31) warp_sums[wid] = incl;
        __syncthreads();
        if (wid == 0) {
            int ws = warp_sums[lane];
#pragma unroll
            for (int o = 1; o < 32; o <<= 1) {
                int u = __shfl_up_sync(0xffffffffu, ws, o);
                if (lane >= o) ws += u;
            }
            warp_sums[lane] = ws;
        }
        __syncthreads();
        int excl = incl - tsum + (wid > 0 ? warp_sums[wid - 1] : 0) + s_carry;
        if (i < nInt4) {
            int4 o4;
            o4.x = excl;
            o4.y = excl + v[t].x;
            o4.z = excl + s01;
            o4.w = excl + s01 + v[t].z;
            off4[i] = o4;
        }
        __syncthreads();
        if (tid == 0) s_carry += warp_sums[31];
        __syncthreads();
    }
    if (tid == 0) g_off[NN] = s_carry;
}

// === self-loops + edge fill: no atomics; ONE packed 8B store per entry ===
__global__ void k_fillself(const void* __restrict__ ei) {
    int t = blockIdx.x * blockDim.x + threadIdx.x;
    if (t < NN) {
        int o = g_off[t];
        g_ed[o] = make_int2(t, __float_as_int(1.0f / (float)g_cnt[t]));
    } else if (t < NN + NE) {
        int e = t - NN;
        int r = edge_val(ei, 0, e);
        int c = edge_val(ei, 1, e);
        int s = g_off[c] + g_slot[e];
        float w = rsqrtf((float)g_cnt[r]) * rsqrtf((float)g_cnt[c]);
        g_ed[s] = make_int2(r, __float_as_int(w));
    }
}

// ============== fp16 GEMM: 32x64 warp tile, 3-stage, 2 CTAs/SM ==========
template<int K>
__global__ __launch_bounds__(256, 2) void k_mma(
    const __half* __restrict__ Af, const __half* __restrict__ Bt,
    __half* __restrict__ C, int M, int Nc)
{
    constexpr int BK = 32;
    constexpr int NC_CHUNK = K / BK;
    constexpr int SA = BK + 8;
    constexpr int QTR = 128 * SA * 2;
    constexpr int STAGE = 2 * QTR;

    extern __shared__ char smem[];
    uint32_t smem_base = smem_to_u32(smem);
    int tid = threadIdx.x;
    int lane = tid & 31;
    int wid = tid >> 5;
    int bm = blockIdx.y * 128;
    int bn = blockIdx.x * 128;
    int wm = (wid >> 1) * 32;
    int wn = (wid & 1) * 64;
    int lt = lane >> 3;
    int lr = lane & 7;

    uint32_t a_base[2];
#pragma unroll
    for (int mi = 0; mi < 2; mi++)
        a_base[mi] = smem_base +
            ((wm + mi * 16 + (lt & 1) * 8 + lr) * SA + (lt >> 1) * 8) * 2;
    uint32_t b_base[4];
#pragma unroll
    for (int nj = 0; nj < 4; nj++)
        b_base[nj] = smem_base + QTR +
            ((wn + nj * 16 + (lt >> 1) * 8 + lr) * SA + (lt & 1) * 8) * 2;

    auto issue_chunk = [&](int c) {
        uint32_t dst = smem_base + (uint32_t)(c % 3) * STAGE;
#pragma unroll
        for (int t = 0; t < 4; t++) {
            int i = tid + t * 256;
            if (i < 512) {
                int m = i >> 2, k = (i & 3) * 8;
                int gm = bm + m;
                if (gm > M - 1) gm = M - 1;
                CP_ASYNC16(dst + (m * SA + k) * 2,
                           Af + (size_t)gm * K + c * BK + k);
            } else {
                int j = i - 512;
                int n = j >> 2, k = (j & 3) * 8;
                CP_ASYNC16(dst + QTR + (n * SA + k) * 2,
                           Bt + (size_t)(bn + n) * K + c * BK + k);
            }
        }
    };

    float acc[2][8][4];
#pragma unroll
    for (int mi = 0; mi < 2; mi++)
#pragma unroll
        for (int ni = 0; ni < 8; ni++)
#pragma unroll
            for (int v = 0; v < 4; v++) acc[mi][ni][v] = 0.f;

    issue_chunk(0); CP_COMMIT();
    if (NC_CHUNK > 1) { issue_chunk(1); CP_COMMIT(); }

    for (int c = 0; c < NC_CHUNK; c++) {
        if (c + 1 < NC_CHUNK) CP_WAIT1(); else CP_WAIT0();
        __syncthreads();
        if (c + 2 < NC_CHUNK) { issue_chunk(c + 2); CP_COMMIT(); }

        uint32_t sbuf = (uint32_t)(c % 3) * STAGE;
#pragma unroll
        for (int ks = 0; ks < BK / 16; ks++) {
            uint32_t o = sbuf + ks * 32;
            uint32_t af[2][4];
            LDSM4(af[0], a_base[0] + o);
            LDSM4(af[1], a_base[1] + o);
            uint32_t bB[2][4];
            LDSM4(bB[0], b_base[0] + o);
#pragma unroll
            for (int nj = 0; nj < 4; nj++) {
                int cur = nj & 1, nxt = cur ^ 1;
                if (nj < 3) LDSM4(bB[nxt], b_base[nj + 1] + o);
                MMA_FP16(acc[0][2 * nj],     af[0], bB[cur][0], bB[cur][1]);
                MMA_FP16(acc[1][2 * nj],     af[1], bB[cur][0], bB[cur][1]);
                MMA_FP16(acc[0][2 * nj + 1], af[0], bB[cur][2], bB[cur][3]);
                MMA_FP16(acc[1][2 * nj + 1], af[1], bB[cur][2], bB[cur][3]);
            }
        }
    }

    int g = lane >> 2, tg = lane & 3;
#pragma unroll
    for (int mi = 0; mi < 2; mi++) {
        int r0 = bm + wm + mi * 16 + g;
#pragma unroll
        for (int ni = 0; ni < 8; ni++) {
            int col = bn + wn + ni * 8 + tg * 2;
            __half2 v0 = __floats2half2_rn(acc[mi][ni][0], acc[mi][ni][1]);
            __half2 v1 = __floats2half2_rn(acc[mi][ni][2], acc[mi][ni][3]);
            if (r0 < M)     *(__half2*)(C + (size_t)r0 * Nc + col) = v0;
            if (r0 + 8 < M) *(__half2*)(C + (size_t)(r0 + 8) * Nc + col) = v1;
        }
    }
}

// ======== head GEMM with fused relu + Wf2 reduction ========
__global__ __launch_bounds__(256, 2) void k_head(
    const __half* __restrict__ Af, const __half* __restrict__ Bt,
    const float* __restrict__ bias, int M,
    const float* __restrict__ wf2, const float* __restrict__ bf2,
    float* __restrict__ outp)
{
    constexpr int K = 256;
    constexpr int BK = 32;
    constexpr int NC_CHUNK = K / BK;
    constexpr int SA = BK + 8;
    constexpr int QTR = 128 * SA * 2;
    constexpr int STAGE = 2 * QTR;

    extern __shared__ char smem[];
    __shared__ float red[128];
    uint32_t smem_base = smem_to_u32(smem);
    int tid = threadIdx.x;
    int lane = tid & 31;
    int wid = tid >> 5;
    int bm = blockIdx.x * 128;
    int wm = (wid >> 1) * 32;
    int wn = (wid & 1) * 64;
    int lt = lane >> 3;
    int lr = lane & 7;

    if (tid < 128) red[tid] = 0.f;

    uint32_t a_base[2];
#pragma unroll
    for (int mi = 0; mi < 2; mi++)
        a_base[mi] = smem_base +
            ((wm + mi * 16 + (lt & 1) * 8 + lr) * SA + (lt >> 1) * 8) * 2;
    uint32_t b_base[4];
#pragma unroll
    for (int nj = 0; nj < 4; nj++)
        b_base[nj] = smem_base + QTR +
            ((wn + nj * 16 + (lt >> 1) * 8 + lr) * SA + (lt & 1) * 8) * 2;

    auto issue_chunk = [&](int c) {
        uint32_t dst = smem_base + (uint32_t)(c % 3) * STAGE;
#pragma unroll
        for (int t = 0; t < 4; t++) {
            int i = tid + t * 256;
            if (i < 512) {
                int m = i >> 2, k = (i & 3) * 8;
                int gm = bm + m;
                if (gm > M - 1) gm = M - 1;
                CP_ASYNC16(dst + (m * SA + k) * 2,
                           Af + (size_t)gm * K + c * BK + k);
            } else {
                int j = i - 512;
                int n = j >> 2, k = (j & 3) * 8;
                CP_ASYNC16(dst + QTR + (n * SA + k) * 2,
                           Bt + (size_t)n * K + c * BK + k);
            }
        }
    };

    float acc[2][8][4];
#pragma unroll
    for (int mi = 0; mi < 2; mi++)
#pragma unroll
        for (int ni = 0; ni < 8; ni++)
#pragma unroll
            for (int v = 0; v < 4; v++) acc[mi][ni][v] = 0.f;

    issue_chunk(0); CP_COMMIT();
    issue_chunk(1); CP_COMMIT();

    for (int c = 0; c < NC_CHUNK; c++) {
        if (c + 1 < NC_CHUNK) CP_WAIT1(); else CP_WAIT0();
        __syncthreads();
        if (c + 2 < NC_CHUNK) { issue_chunk(c + 2); CP_COMMIT(); }

        uint32_t sbuf = (uint32_t)(c % 3) * STAGE;
#pragma unroll
        for (int ks = 0; ks < BK / 16; ks++) {
            uint32_t o = sbuf + ks * 32;
            uint32_t af[2][4];
            LDSM4(af[0], a_base[0] + o);
            LDSM4(af[1], a_base[1] + o);
            uint32_t bB[2][4];
            LDSM4(bB[0], b_base[0] + o);
#pragma unroll
            for (int nj = 0; nj < 4; nj++) {
                int cur = nj & 1, nxt = cur ^ 1;
                if (nj < 3) LDSM4(bB[nxt], b_base[nj + 1] + o);
                MMA_FP16(acc[0][2 * nj],     af[0], bB[cur][0], bB[cur][1]);
                MMA_FP16(acc[1][2 * nj],     af[1], bB[cur][0], bB[cur][1]);
                MMA_FP16(acc[0][2 * nj + 1], af[0], bB[cur][2], bB[cur][3]);
                MMA_FP16(acc[1][2 * nj + 1], af[1], bB[cur][2], bB[cur][3]);
            }
        }
    }

    int g = lane >> 2, tg = lane & 3;
    __syncthreads();
#pragma unroll
    for (int mi = 0; mi < 2; mi++) {
        float p0 = 0.f, p1 = 0.f;
#pragma unroll
        for (int ni = 0; ni < 8; ni++) {
            int col = wn + ni * 8 + tg * 2;
            float bx = bias[col], by = bias[col + 1];
            float w0 = wf2[col], w1 = wf2[col + 1];
            p0 += fmaxf(acc[mi][ni][0] + bx, 0.f) * w0
                + fmaxf(acc[mi][ni][1] + by, 0.f) * w1;
            p1 += fmaxf(acc[mi][ni][2] + bx, 0.f) * w0
                + fmaxf(acc[mi][ni][3] + by, 0.f) * w1;
        }
        atomicAdd(&red[wm + mi * 16 + g], p0);
        atomicAdd(&red[wm + mi * 16 + 8 + g], p1);
    }
    __syncthreads();
    if (tid < 128) {
        int r = bm + tid;
        if (r < M) outp[r] = red[tid] + bf2[0];
    }
}

// ======== fused aggregate(+bias)+LN+ReLU+residual, fp16 gather ========
// Edge records packed as int2 (src, nrm-bits): one broadcast load per edge.
template<int MODE>
__global__ __launch_bounds__(256) void k_agg(
    const __half* __restrict__ xw, const float* __restrict__ bias,
    const float* __restrict__ gam, const float* __restrict__ bet,
    const __half* __restrict__ prev, __half* __restrict__ outp)
{
    int n = (blockIdx.x * blockDim.x + threadIdx.x) >> 5;
    int lane = threadIdx.x & 31;
    if (n >= NN) return;
    int s0 = g_off[n], s1 = g_off[n + 1];
    float a[8] = {0.f, 0.f, 0.f, 0.f, 0.f, 0.f, 0.f, 0.f};
    int s = s0;

    auto accum = [&](uint4 raw, float w) {
        union { uint4 u; __half2 h[4]; } cv;
        cv.u = raw;
#pragma unroll
        for (int q = 0; q < 4; q++) {
            float2 f = __half22float2(cv.h[q]);
            a[2 * q]     += w * f.x;
            a[2 * q + 1] += w * f.y;
        }
    };

    for (; s + 3 < s1; s += 4) {
        int2 e0 = g_ed[s],     e1 = g_ed[s + 1];
        int2 e2 = g_ed[s + 2], e3 = g_ed[s + 3];
        uint4 r0 = ((const uint4*)(xw + (size_t)e0.x * HD))[lane];
        uint4 r1 = ((const uint4*)(xw + (size_t)e1.x * HD))[lane];
        uint4 r2 = ((const uint4*)(xw + (size_t)e2.x * HD))[lane];
        uint4 r3 = ((const uint4*)(xw + (size_t)e3.x * HD))[lane];
        accum(r0, __int_as_float(e0.y));
        accum(r1, __int_as_float(e1.y));
        accum(r2, __int_as_float(e2.y));
        accum(r3, __int_as_float(e3.y));
    }
    for (; s < s1; s++) {
        int2 e0 = g_ed[s];
        uint4 r0 = ((const uint4*)(xw + (size_t)e0.x * HD))[lane];
        accum(r0, __int_as_float(e0.y));
    }

    const float4* bp = (const float4*)bias + (lane << 1);
    float4 b0 = bp[0], b1 = bp[1];
    a[0] += b0.x; a[1] += b0.y; a[2] += b0.z; a[3] += b0.w;
    a[4] += b1.x; a[5] += b1.y; a[6] += b1.z; a[7] += b1.w;

    float sm = 0.f, sq = 0.f;
#pragma unroll
    for (int i = 0; i < 8; i++) { sm += a[i]; sq += a[i] * a[i]; }
#pragma unroll
    for (int o = 16; o > 0; o >>= 1) {
        sm += __shfl_xor_sync(0xffffffffu, sm, o);
        sq += __shfl_xor_sync(0xffffffffu, sq, o);
    }
    float mu = sm * (1.f / HD);
    float inv = rsqrtf(sq * (1.f / HD) - mu * mu + EPSV);

    const float4* gp = (const float4*)gam + (lane << 1);
    const float4* ep = (const float4*)bet + (lane << 1);
    float4 gg0 = gp[0], gg1 = gp[1], ee0 = ep[0], ee1 = ep[1];
    float gv[8] = { gg0.x, gg0.y, gg0.z, gg0.w, gg1.x, gg1.y, gg1.z, gg1.w };
    float ev[8] = { ee0.x, ee0.y, ee0.z, ee0.w, ee1.x, ee1.y, ee1.z, ee1.w };
    float r[8];
#pragma unroll
    for (int i = 0; i < 8; i++)
        r[i] = fmaxf((a[i] - mu) * inv * gv[i] + ev[i], 0.f);

    size_t obase = (size_t)n * HD + lane * 8;
    if (MODE == 2 || MODE == 3) {
        union { uint4 u; __half h[8]; } pu;
        pu.u = *(const uint4*)(prev + obase);
#pragma unroll
        for (int i = 0; i < 8; i++) {
            float pv = __half2float(pu.h[i]);
            r[i] = (MODE == 2) ? (r[i] + 0.7f * pv) : (r[i] * 0.7f + pv);
        }
    }

    union { __half h[8]; uint4 u; } uo;
#pragma unroll
    for (int i = 0; i < 8; i++) uo.h[i] = __float2half_rn(r[i]);
    *(uint4*)(outp + obase) = uo.u;
}

// ==================== orchestration ====================
extern "C" void kernel_launch(void* const* d_in, const int* in_sizes, int n_in,
                              void* d_out, int out_size)
{
    const float* x   = (const float*)d_in[0];
    const void*  ei  = d_in[1];
    const float* W1  = (const float*)d_in[2];
    const float* b1  = (const float*)d_in[3];
    const float* g1  = (const float*)d_in[4];
    const float* be1 = (const float*)d_in[5];
    const float* W2  = (const float*)d_in[6];
    const float* b2  = (const float*)d_in[7];
    const float* g2  = (const float*)d_in[8];
    const float* be2 = (const float*)d_in[9];
    const float* W3  = (const float*)d_in[10];
    const float* b3  = (const float*)d_in[11];
    const float* g3  = (const float*)d_in[12];
    const float* be3 = (const float*)d_in[13];
    const float* Wf1 = (const float*)d_in[14];
    const float* bf1 = (const float*)d_in[15];
    const float* Wf2 = (const float*)d_in[16];
    const float* bf2 = (const float*)d_in[17];
    float* out = (float*)d_out;

    __half *xw_p, *af, *w1t, *w2t, *w3t, *wft;
    cudaGetSymbolAddress((void**)&xw_p, g_xw);
    cudaGetSymbolAddress((void**)&af, g_af);
    cudaGetSymbolAddress((void**)&w1t, g_w1t);
    cudaGetSymbolAddress((void**)&w2t, g_w2t);
    cudaGetSymbolAddress((void**)&w3t, g_w3t);
    cudaGetSymbolAddress((void**)&wft, g_wf1t);

    const int SMEM = 3 * 20480;
    cudaFuncSetAttribute(k_mma<128>, cudaFuncAttributeMaxDynamicSharedMemorySize, SMEM);
    cudaFuncSetAttribute(k_mma<256>, cudaFuncAttributeMaxDynamicSharedMemorySize, SMEM);
    cudaFuncSetAttribute(k_head,     cudaFuncAttributeMaxDynamicSharedMemorySize, SMEM);

    static cudaStream_t s2 = nullptr;
    static cudaEvent_t evFork = nullptr, evJoin = nullptr;
    if (s2 == nullptr) {
        cudaStreamCreateWithFlags(&s2, cudaStreamNonBlocking);
        cudaEventCreateWithFlags(&evFork, cudaEventDisableTiming);
        cudaEventCreateWithFlags(&evJoin, cudaEventDisableTiming);
    }

    const int TB = 256;
    int gWarp = (NN * 32 + TB - 1) / TB;
    int mBlocks = (NN + 127) / 128;

    // ---- fork: side stream builds CSR while main stream does cvt + GEMM1 ----
    cudaEventRecord(evFork, 0);
    cudaStreamWaitEvent(s2, evFork, 0);

    // side stream: init+detect -> deg(+slot) -> scan -> fill (packed, no atomics)
    k_init<<<(NN + TB - 1) / TB, TB, 0, s2>>>((const int*)ei);
    k_deg<<<(NE + TB - 1) / TB, TB, 0, s2>>>(ei);
    k_scan<<<1, 1024, 0, s2>>>();
    k_fillself<<<(NN + NE + TB - 1) / TB, TB, 0, s2>>>(ei);
    cudaEventRecord(evJoin, s2);

    // main stream: x/weights convert -> layer-1 GEMM
    k_cvtw<<<(NN * 128 + TB - 1) / TB, TB>>>(x, W1, W2, W3, Wf1,
                                             af, w1t, w2t, w3t, wft);
    k_mma<128><<<dim3(2, mBlocks), 256, SMEM>>>(af, w1t, xw_p, NN, 256);

    // join
    cudaStreamWaitEvent(0, evJoin, 0);

    k_agg<1><<<gWarp, TB>>>(xw_p, b1, g1, be1, nullptr, af);

    k_mma<256><<<dim3(2, mBlocks), 256, SMEM>>>(af, w2t, xw_p, NN, 256);
    k_agg<2><<<gWarp, TB>>>(xw_p, b2, g2, be2, af, af);

    k_mma<256><<<dim3(2, mBlocks), 256, SMEM>>>(af, w3t, xw_p, NN, 256);
    k_agg<3><<<gWarp, TB>>>(xw_p, b3, g3, be3, af, af);

    k_head<<<mBlocks, 256, SMEM>>>(af, wft, bf1, NN, Wf2, bf2, out);
}

// round 17
// speedup vs baseline: 1.1099x; 1.0887x over previous
#include <cuda_runtime.h>
#include <cuda_fp16.h>
#include <cstdint>

#define NN 50000
#define NE 800000
#define NM (NE + NN)
#define HD 256
#define EPSV 1e-5f

// ==================== PTX helpers ====================
#define LDSM4(r, addr) asm volatile( \
    "ldmatrix.sync.aligned.m8n8.x4.shared.b16 {%0,%1,%2,%3}, [%4];" \
    : "=r"((r)[0]), "=r"((r)[1]), "=r"((r)[2]), "=r"((r)[3]) : "r"(addr))

#define MMA_FP16(d, a, b0, b1) asm volatile( \
    "mma.sync.aligned.m16n8k16.row.col.f32.f16.f16.f32 " \
    "{%0,%1,%2,%3}, {%4,%5,%6,%7}, {%8,%9}, {%0,%1,%2,%3};" \
    : "+f"((d)[0]), "+f"((d)[1]), "+f"((d)[2]), "+f"((d)[3]) \
    : "r"((a)[0]), "r"((a)[1]), "r"((a)[2]), "r"((a)[3]), "r"(b0), "r"(b1))

#define CP_ASYNC16(dst, src) \
    asm volatile("cp.async.cg.shared.global [%0], [%1], 16;" :: "r"(dst), "l"(src))
#define CP_COMMIT() asm volatile("cp.async.commit_group;" ::: "memory")
#define CP_WAIT1() asm volatile("cp.async.wait_group 1;" ::: "memory")
#define CP_WAIT0() asm volatile("cp.async.wait_group 0;" ::: "memory")

__device__ __forceinline__ uint32_t smem_to_u32(const void* smem_ptr) {
    uint32_t addr;
    asm("{ .reg .u64 tmp; cvta.to.shared.u64 tmp, %1; cvt.u32.u64 %0, tmp; }"
        : "=r"(addr) : "l"(smem_ptr));
    return addr;
}

// ==================== device scratch ====================
__device__ __align__(256) __half g_xw[(size_t)NN * HD];
__device__ __align__(256) __half g_af[(size_t)NN * HD];
__device__ __align__(256) __half g_w1t[256 * 128];
__device__ __align__(256) __half g_w2t[256 * 256];
__device__ __align__(256) __half g_w3t[256 * 256];
__device__ __align__(256) __half g_wf1t[128 * 256];
__device__ __align__(16) int  g_cnt[NN];
__device__ __align__(16) int  g_off[NN + 4];
__device__ __align__(16) int  g_slot[NE];   // per-edge slot within its target row
__device__ __align__(16) int2 g_ed[NM];     // packed (src, nrm-bits) per CSR entry
__device__ int  g_is64;

__device__ __forceinline__ int edge_val(const void* ei, int which, int e) {
    if (g_is64) return (int)((const long long*)ei)[(size_t)which * NE + e];
    return ((const int*)ei)[(size_t)which * NE + e];
}

// ==== main-stream prologue: x->fp16 (vectorized) + weight transpose+fp16 ====
__global__ void k_cvtw(
    const float* __restrict__ x,
    const float* __restrict__ W1, const float* __restrict__ W2,
    const float* __restrict__ W3, const float* __restrict__ Wf1,
    __half* __restrict__ Af,
    __half* __restrict__ w1t, __half* __restrict__ w2t,
    __half* __restrict__ w3t, __half* __restrict__ wft)
{
    int idx = blockIdx.x * blockDim.x + threadIdx.x;
    // x -> fp16, 8 elems/thread (NN*128 = 6.4M, exactly divisible by 8)
    if (idx < NN * 128 / 8) {
        const float4* xp = (const float4*)x + idx * 2;
        float4 v0 = xp[0], v1 = xp[1];
        union { __half h[8]; uint4 u; } o;
        o.h[0] = __float2half_rn(v0.x); o.h[1] = __float2half_rn(v0.y);
        o.h[2] = __float2half_rn(v0.z); o.h[3] = __float2half_rn(v0.w);
        o.h[4] = __float2half_rn(v1.x); o.h[5] = __float2half_rn(v1.y);
        o.h[6] = __float2half_rn(v1.z); o.h[7] = __float2half_rn(v1.w);
        *((uint4*)Af + idx) = o.u;
    }
    if (idx < 196608) {
        const float* W; __half* T; int K, Nc, local;
        if (idx < 32768)       { W = W1;  T = w1t; K = 128; Nc = 256; local = idx; }
        else if (idx < 98304)  { W = W2;  T = w2t; K = 256; Nc = 256; local = idx - 32768; }
        else if (idx < 163840) { W = W3;  T = w3t; K = 256; Nc = 256; local = idx - 98304; }
        else                   { W = Wf1; T = wft; K = 256; Nc = 128; local = idx - 163840; }
        int k = local / Nc, n = local % Nc;
        T[(size_t)n * K + k] = __float2half_rn(W[local]);
    }
}

// ==== side-stream: cnt init + edge dtype detect ====
__global__ void k_init(const int* __restrict__ eip) {
    int idx = blockIdx.x * blockDim.x + threadIdx.x;
    if (idx < NN) g_cnt[idx] = 1;     // self-loop occupies slot 0
    if (blockIdx.x == 0 && threadIdx.x < 32) {
        int lane = threadIdx.x;
        int nz = 0;
        for (int j = lane; j < 1024; j += 32) nz |= eip[2 * j + 1];
        unsigned any = __ballot_sync(0xffffffffu, nz != 0);
        if (lane == 0) g_is64 = (any == 0) ? 1 : 0;
    }
}

// ==== degree histogram: 2 edges/thread, one vector load, packed slot store ==
__global__ void k_deg(const void* __restrict__ ei) {
    int t = blockIdx.x * blockDim.x + threadIdx.x;
    int e0 = t * 2;
    if (e0 + 1 < NE) {
        int c0, c1;
        if (g_is64) {
            // two int64 cols in one 16B load
            const int4 v = *(const int4*)((const long long*)ei + NE + e0);
            c0 = v.x;   // low word of first int64
            c1 = v.z;   // low word of second int64
        } else {
            const int2 v = *(const int2*)((const int*)ei + NE + e0);
            c0 = v.x; c1 = v.y;
        }
        int p0 = atomicAdd(&g_cnt[c0], 1);
        int p1 = atomicAdd(&g_cnt[c1], 1);
        *(int2*)(g_slot + e0) = make_int2(p0, p1);
    } else if (e0 < NE) {
        int c = edge_val(ei, 1, e0);
        g_slot[e0] = atomicAdd(&g_cnt[c], 1);
    }
}

// ===== single-block scan: ALL tiles prefetched to regs, shuffle+carry =====
__global__ void k_scan() {
    __shared__ int warp_sums[32];
    __shared__ int s_carry;
    constexpr int nInt4 = NN / 4;
    constexpr int NT = (nInt4 + 1023) / 1024;
    int tid = threadIdx.x;
    int lane = tid & 31, wid = tid >> 5;
    const int4* cnt4 = (const int4*)g_cnt;
    int4* off4 = (int4*)g_off;

    int4 v[NT];
#pragma unroll
    for (int t = 0; t < NT; t++) {
        int i = t * 1024 + tid;
        v[t] = (i < nInt4) ? cnt4[i] : make_int4(0, 0, 0, 0);
    }
    if (tid == 0) s_carry = 0;
    __syncthreads();

#pragma unroll
    for (int t = 0; t < NT; t++) {
        int i = t * 1024 + tid;
        int s01 = v[t].x + v[t].y;
        int tsum = s01 + v[t].z + v[t].w;
        int incl = tsum;
#pragma unroll
        for (int o = 1; o < 32; o <<= 1) {
            int u = __shfl_up_sync(0xffffffffu, incl, o);
            if (lane >= o) incl += u;
        }
        if (lane == 31) warp_sums[wid] = incl;
        __syncthreads();
        if (wid == 0) {
            int ws = warp_sums[lane];
#pragma unroll
            for (int o = 1; o < 32; o <<= 1) {
                int u = __shfl_up_sync(0xffffffffu, ws, o);
                if (lane >= o) ws += u;
            }
            warp_sums[lane] = ws;
        }
        __syncthreads();
        int excl = incl - tsum + (wid > 0 ? warp_sums[wid - 1] : 0) + s_carry;
        if (i < nInt4) {
            int4 o4;
            o4.x = excl;
            o4.y = excl + v[t].x;
            o4.z = excl + s01;
            o4.w = excl + s01 + v[t].z;
            off4[i] = o4;
        }
        __syncthreads();
        if (tid == 0) s_carry += warp_sums[31];
        __syncthreads();
    }
    if (tid == 0) g_off[NN] = s_carry;
}

// === self-loops + edge fill: no atomics; ONE packed 8B store per entry ===
__global__ void k_fillself(const void* __restrict__ ei) {
    int t = blockIdx.x * blockDim.x + threadIdx.x;
    if (t < NN) {
        int o = g_off[t];
        g_ed[o] = make_int2(t, __float_as_int(1.0f / (float)g_cnt[t]));
    } else if (t < NN + NE) {
        int e = t - NN;
        int r = edge_val(ei, 0, e);
        int c = edge_val(ei, 1, e);
        int s = g_off[c] + g_slot[e];
        float w = rsqrtf((float)g_cnt[r]) * rsqrtf((float)g_cnt[c]);
        g_ed[s] = make_int2(r, __float_as_int(w));
    }
}

// ============== fp16 GEMM: 32x64 warp tile, 3-stage, 2 CTAs/SM ==========
template<int K>
__global__ __launch_bounds__(256, 2) void k_mma(
    const __half* __restrict__ Af, const __half* __restrict__ Bt,
    __half* __restrict__ C, int M, int Nc)
{
    constexpr int BK = 32;
    constexpr int NC_CHUNK = K / BK;
    constexpr int SA = BK + 8;
    constexpr int QTR = 128 * SA * 2;
    constexpr int STAGE = 2 * QTR;

    extern __shared__ char smem[];
    uint32_t smem_base = smem_to_u32(smem);
    int tid = threadIdx.x;
    int lane = tid & 31;
    int wid = tid >> 5;
    int bm = blockIdx.y * 128;
    int bn = blockIdx.x * 128;
    int wm = (wid >> 1) * 32;
    int wn = (wid & 1) * 64;
    int lt = lane >> 3;
    int lr = lane & 7;

    uint32_t a_base[2];
#pragma unroll
    for (int mi = 0; mi < 2; mi++)
        a_base[mi] = smem_base +
            ((wm + mi * 16 + (lt & 1) * 8 + lr) * SA + (lt >> 1) * 8) * 2;
    uint32_t b_base[4];
#pragma unroll
    for (int nj = 0; nj < 4; nj++)
        b_base[nj] = smem_base + QTR +
            ((wn + nj * 16 + (lt >> 1) * 8 + lr) * SA + (lt & 1) * 8) * 2;

    auto issue_chunk = [&](int c) {
        uint32_t dst = smem_base + (uint32_t)(c % 3) * STAGE;
#pragma unroll
        for (int t = 0; t < 4; t++) {
            int i = tid + t * 256;
            if (i < 512) {
                int m = i >> 2, k = (i & 3) * 8;
                int gm = bm + m;
                if (gm > M - 1) gm = M - 1;
                CP_ASYNC16(dst + (m * SA + k) * 2,
                           Af + (size_t)gm * K + c * BK + k);
            } else {
                int j = i - 512;
                int n = j >> 2, k = (j & 3) * 8;
                CP_ASYNC16(dst + QTR + (n * SA + k) * 2,
                           Bt + (size_t)(bn + n) * K + c * BK + k);
            }
        }
    };

    float acc[2][8][4];
#pragma unroll
    for (int mi = 0; mi < 2; mi++)
#pragma unroll
        for (int ni = 0; ni < 8; ni++)
#pragma unroll
            for (int v = 0; v < 4; v++) acc[mi][ni][v] = 0.f;

    issue_chunk(0); CP_COMMIT();
    if (NC_CHUNK > 1) { issue_chunk(1); CP_COMMIT(); }

    for (int c = 0; c < NC_CHUNK; c++) {
        if (c + 1 < NC_CHUNK) CP_WAIT1(); else CP_WAIT0();
        __syncthreads();
        if (c + 2 < NC_CHUNK) { issue_chunk(c + 2); CP_COMMIT(); }

        uint32_t sbuf = (uint32_t)(c % 3) * STAGE;
#pragma unroll
        for (int ks = 0; ks < BK / 16; ks++) {
            uint32_t o = sbuf + ks * 32;
            uint32_t af[2][4];
            LDSM4(af[0], a_base[0] + o);
            LDSM4(af[1], a_base[1] + o);
            uint32_t bB[2][4];
            LDSM4(bB[0], b_base[0] + o);
#pragma unroll
            for (int nj = 0; nj < 4; nj++) {
                int cur = nj & 1, nxt = cur ^ 1;
                if (nj < 3) LDSM4(bB[nxt], b_base[nj + 1] + o);
                MMA_FP16(acc[0][2 * nj],     af[0], bB[cur][0], bB[cur][1]);
                MMA_FP16(acc[1][2 * nj],     af[1], bB[cur][0], bB[cur][1]);
                MMA_FP16(acc[0][2 * nj + 1], af[0], bB[cur][2], bB[cur][3]);
                MMA_FP16(acc[1][2 * nj + 1], af[1], bB[cur][2], bB[cur][3]);
            }
        }
    }

    int g = lane >> 2, tg = lane & 3;
#pragma unroll
    for (int mi = 0; mi < 2; mi++) {
        int r0 = bm + wm + mi * 16 + g;
#pragma unroll
        for (int ni = 0; ni < 8; ni++) {
            int col = bn + wn + ni * 8 + tg * 2;
            __half2 v0 = __floats2half2_rn(acc[mi][ni][0], acc[mi][ni][1]);
            __half2 v1 = __floats2half2_rn(acc[mi][ni][2], acc[mi][ni][3]);
            if (r0 < M)     *(__half2*)(C + (size_t)r0 * Nc + col) = v0;
            if (r0 + 8 < M) *(__half2*)(C + (size_t)(r0 + 8) * Nc + col) = v1;
        }
    }
}

// ======== head GEMM with fused relu + Wf2 reduction ========
__global__ __launch_bounds__(256, 2) void k_head(
    const __half* __restrict__ Af, const __half* __restrict__ Bt,
    const float* __restrict__ bias, int M,
    const float* __restrict__ wf2, const float* __restrict__ bf2,
    float* __restrict__ outp)
{
    constexpr int K = 256;
    constexpr int BK = 32;
    constexpr int NC_CHUNK = K / BK;
    constexpr int SA = BK + 8;
    constexpr int QTR = 128 * SA * 2;
    constexpr int STAGE = 2 * QTR;

    extern __shared__ char smem[];
    __shared__ float red[128];
    uint32_t smem_base = smem_to_u32(smem);
    int tid = threadIdx.x;
    int lane = tid & 31;
    int wid = tid >> 5;
    int bm = blockIdx.x * 128;
    int wm = (wid >> 1) * 32;
    int wn = (wid & 1) * 64;
    int lt = lane >> 3;
    int lr = lane & 7;

    if (tid < 128) red[tid] = 0.f;

    uint32_t a_base[2];
#pragma unroll
    for (int mi = 0; mi < 2; mi++)
        a_base[mi] = smem_base +
            ((wm + mi * 16 + (lt & 1) * 8 + lr) * SA + (lt >> 1) * 8) * 2;
    uint32_t b_base[4];
#pragma unroll
    for (int nj = 0; nj < 4; nj++)
        b_base[nj] = smem_base + QTR +
            ((wn + nj * 16 + (lt >> 1) * 8 + lr) * SA + (lt & 1) * 8) * 2;

    auto issue_chunk = [&](int c) {
        uint32_t dst = smem_base + (uint32_t)(c % 3) * STAGE;
#pragma unroll
        for (int t = 0; t < 4; t++) {
            int i = tid + t * 256;
            if (i < 512) {
                int m = i >> 2, k = (i & 3) * 8;
                int gm = bm + m;
                if (gm > M - 1) gm = M - 1;
                CP_ASYNC16(dst + (m * SA + k) * 2,
                           Af + (size_t)gm * K + c * BK + k);
            } else {
                int j = i - 512;
                int n = j >> 2, k = (j & 3) * 8;
                CP_ASYNC16(dst + QTR + (n * SA + k) * 2,
                           Bt + (size_t)n * K + c * BK + k);
            }
        }
    };

    float acc[2][8][4];
#pragma unroll
    for (int mi = 0; mi < 2; mi++)
#pragma unroll
        for (int ni = 0; ni < 8; ni++)
#pragma unroll
            for (int v = 0; v < 4; v++) acc[mi][ni][v] = 0.f;

    issue_chunk(0); CP_COMMIT();
    issue_chunk(1); CP_COMMIT();

    for (int c = 0; c < NC_CHUNK; c++) {
        if (c + 1 < NC_CHUNK) CP_WAIT1(); else CP_WAIT0();
        __syncthreads();
        if (c + 2 < NC_CHUNK) { issue_chunk(c + 2); CP_COMMIT(); }

        uint32_t sbuf = (uint32_t)(c % 3) * STAGE;
#pragma unroll
        for (int ks = 0; ks < BK / 16; ks++) {
            uint32_t o = sbuf + ks * 32;
            uint32_t af[2][4];
            LDSM4(af[0], a_base[0] + o);
            LDSM4(af[1], a_base[1] + o);
            uint32_t bB[2][4];
            LDSM4(bB[0], b_base[0] + o);
#pragma unroll
            for (int nj = 0; nj < 4; nj++) {
                int cur = nj & 1, nxt = cur ^ 1;
                if (nj < 3) LDSM4(bB[nxt], b_base[nj + 1] + o);
                MMA_FP16(acc[0][2 * nj],     af[0], bB[cur][0], bB[cur][1]);
                MMA_FP16(acc[1][2 * nj],     af[1], bB[cur][0], bB[cur][1]);
                MMA_FP16(acc[0][2 * nj + 1], af[0], bB[cur][2], bB[cur][3]);
                MMA_FP16(acc[1][2 * nj + 1], af[1], bB[cur][2], bB[cur][3]);
            }
        }
    }

    int g = lane >> 2, tg = lane & 3;
    __syncthreads();
#pragma unroll
    for (int mi = 0; mi < 2; mi++) {
        float p0 = 0.f, p1 = 0.f;
#pragma unroll
        for (int ni = 0; ni < 8; ni++) {
            int col = wn + ni * 8 + tg * 2;
            float bx = bias[col], by = bias[col + 1];
            float w0 = wf2[col], w1 = wf2[col + 1];
            p0 += fmaxf(acc[mi][ni][0] + bx, 0.f) * w0
                + fmaxf(acc[mi][ni][1] + by, 0.f) * w1;
            p1 += fmaxf(acc[mi][ni][2] + bx, 0.f) * w0
                + fmaxf(acc[mi][ni][3] + by, 0.f) * w1;
        }
        atomicAdd(&red[wm + mi * 16 + g], p0);
        atomicAdd(&red[wm + mi * 16 + 8 + g], p1);
    }
    __syncthreads();
    if (tid < 128) {
        int r = bm + tid;
        if (r < M) outp[r] = red[tid] + bf2[0];
    }
}

// ======== fused aggregate(+bias)+LN+ReLU+residual, fp16 gather ========
template<int MODE>
__global__ __launch_bounds__(256) void k_agg(
    const __half* __restrict__ xw, const float* __restrict__ bias,
    const float* __restrict__ gam, const float* __restrict__ bet,
    const __half* __restrict__ prev, __half* __restrict__ outp)
{
    int n = (blockIdx.x * blockDim.x + threadIdx.x) >> 5;
    int lane = threadIdx.x & 31;
    if (n >= NN) return;
    int s0 = g_off[n], s1 = g_off[n + 1];
    float a[8] = {0.f, 0.f, 0.f, 0.f, 0.f, 0.f, 0.f, 0.f};
    int s = s0;

    auto accum = [&](uint4 raw, float w) {
        union { uint4 u; __half2 h[4]; } cv;
        cv.u = raw;
#pragma unroll
        for (int q = 0; q < 4; q++) {
            float2 f = __half22float2(cv.h[q]);
            a[2 * q]     += w * f.x;
            a[2 * q + 1] += w * f.y;
        }
    };

    for (; s + 3 < s1; s += 4) {
        int2 e0 = g_ed[s],     e1 = g_ed[s + 1];
        int2 e2 = g_ed[s + 2], e3 = g_ed[s + 3];
        uint4 r0 = ((const uint4*)(xw + (size_t)e0.x * HD))[lane];
        uint4 r1 = ((const uint4*)(xw + (size_t)e1.x * HD))[lane];
        uint4 r2 = ((const uint4*)(xw + (size_t)e2.x * HD))[lane];
        uint4 r3 = ((const uint4*)(xw + (size_t)e3.x * HD))[lane];
        accum(r0, __int_as_float(e0.y));
        accum(r1, __int_as_float(e1.y));
        accum(r2, __int_as_float(e2.y));
        accum(r3, __int_as_float(e3.y));
    }
    for (; s < s1; s++) {
        int2 e0 = g_ed[s];
        uint4 r0 = ((const uint4*)(xw + (size_t)e0.x * HD))[lane];
        accum(r0, __int_as_float(e0.y));
    }

    const float4* bp = (const float4*)bias + (lane << 1);
    float4 b0 = bp[0], b1 = bp[1];
    a[0] += b0.x; a[1] += b0.y; a[2] += b0.z; a[3] += b0.w;
    a[4] += b1.x; a[5] += b1.y; a[6] += b1.z; a[7] += b1.w;

    float sm = 0.f, sq = 0.f;
#pragma unroll
    for (int i = 0; i < 8; i++) { sm += a[i]; sq += a[i] * a[i]; }
#pragma unroll
    for (int o = 16; o > 0; o >>= 1) {
        sm += __shfl_xor_sync(0xffffffffu, sm, o);
        sq += __shfl_xor_sync(0xffffffffu, sq, o);
    }
    float mu = sm * (1.f / HD);
    float inv = rsqrtf(sq * (1.f / HD) - mu * mu + EPSV);

    const float4* gp = (const float4*)gam + (lane << 1);
    const float4* ep = (const float4*)bet + (lane << 1);
    float4 gg0 = gp[0], gg1 = gp[1], ee0 = ep[0], ee1 = ep[1];
    float gv[8] = { gg0.x, gg0.y, gg0.z, gg0.w, gg1.x, gg1.y, gg1.z, gg1.w };
    float ev[8] = { ee0.x, ee0.y, ee0.z, ee0.w, ee1.x, ee1.y, ee1.z, ee1.w };
    float r[8];
#pragma unroll
    for (int i = 0; i < 8; i++)
        r[i] = fmaxf((a[i] - mu) * inv * gv[i] + ev[i], 0.f);

    size_t obase = (size_t)n * HD + lane * 8;
    if (MODE == 2 || MODE == 3) {
        union { uint4 u; __half h[8]; } pu;
        pu.u = *(const uint4*)(prev + obase);
#pragma unroll
        for (int i = 0; i < 8; i++) {
            float pv = __half2float(pu.h[i]);
            r[i] = (MODE == 2) ? (r[i] + 0.7f * pv) : (r[i] * 0.7f + pv);
        }
    }

    union { __half h[8]; uint4 u; } uo;
#pragma unroll
    for (int i = 0; i < 8; i++) uo.h[i] = __float2half_rn(r[i]);
    *(uint4*)(outp + obase) = uo.u;
}

// ==================== orchestration ====================
extern "C" void kernel_launch(void* const* d_in, const int* in_sizes, int n_in,
                              void* d_out, int out_size)
{
    const float* x   = (const float*)d_in[0];
    const void*  ei  = d_in[1];
    const float* W1  = (const float*)d_in[2];
    const float* b1  = (const float*)d_in[3];
    const float* g1  = (const float*)d_in[4];
    const float* be1 = (const float*)d_in[5];
    const float* W2  = (const float*)d_in[6];
    const float* b2  = (const float*)d_in[7];
    const float* g2  = (const float*)d_in[8];
    const float* be2 = (const float*)d_in[9];
    const float* W3  = (const float*)d_in[10];
    const float* b3  = (const float*)d_in[11];
    const float* g3  = (const float*)d_in[12];
    const float* be3 = (const float*)d_in[13];
    const float* Wf1 = (const float*)d_in[14];
    const float* bf1 = (const float*)d_in[15];
    const float* Wf2 = (const float*)d_in[16];
    const float* bf2 = (const float*)d_in[17];
    float* out = (float*)d_out;

    __half *xw_p, *af, *w1t, *w2t, *w3t, *wft;
    cudaGetSymbolAddress((void**)&xw_p, g_xw);
    cudaGetSymbolAddress((void**)&af, g_af);
    cudaGetSymbolAddress((void**)&w1t, g_w1t);
    cudaGetSymbolAddress((void**)&w2t, g_w2t);
    cudaGetSymbolAddress((void**)&w3t, g_w3t);
    cudaGetSymbolAddress((void**)&wft, g_wf1t);

    const int SMEM = 3 * 20480;
    cudaFuncSetAttribute(k_mma<128>, cudaFuncAttributeMaxDynamicSharedMemorySize, SMEM);
    cudaFuncSetAttribute(k_mma<256>, cudaFuncAttributeMaxDynamicSharedMemorySize, SMEM);
    cudaFuncSetAttribute(k_head,     cudaFuncAttributeMaxDynamicSharedMemorySize, SMEM);

    static cudaStream_t s2 = nullptr;
    static cudaEvent_t evFork = nullptr, evJoin = nullptr;
    if (s2 == nullptr) {
        cudaStreamCreateWithFlags(&s2, cudaStreamNonBlocking);
        cudaEventCreateWithFlags(&evFork, cudaEventDisableTiming);
        cudaEventCreateWithFlags(&evJoin, cudaEventDisableTiming);
    }

    const int TB = 256;
    int gWarp = (NN * 32 + TB - 1) / TB;
    int mBlocks = (NN + 127) / 128;

    // ---- fork: side stream builds CSR while main stream does cvt + GEMM1 ----
    cudaEventRecord(evFork, 0);
    cudaStreamWaitEvent(s2, evFork, 0);

    // side stream: init+detect -> deg(2 edges/thread) -> scan -> fill
    k_init<<<(NN + TB - 1) / TB, TB, 0, s2>>>((const int*)ei);
    k_deg<<<((NE + 1) / 2 + TB - 1) / TB, TB, 0, s2>>>(ei);
    k_scan<<<1, 1024, 0, s2>>>();
    k_fillself<<<(NN + NE + TB - 1) / TB, TB, 0, s2>>>(ei);
    cudaEventRecord(evJoin, s2);

    // main stream: x/weights convert (vectorized) -> layer-1 GEMM
    k_cvtw<<<(NN * 128 / 8 + TB - 1) / TB, TB>>>(x, W1, W2, W3, Wf1,
                                                 af, w1t, w2t, w3t, wft);
    k_mma<128><<<dim3(2, mBlocks), 256, SMEM>>>(af, w1t, xw_p, NN, 256);

    // join
    cudaStreamWaitEvent(0, evJoin, 0);

    k_agg<1><<<gWarp, TB>>>(xw_p, b1, g1, be1, nullptr, af);

    k_mma<256><<<dim3(2, mBlocks), 256, SMEM>>>(af, w2t, xw_p, NN, 256);
    k_agg<2><<<gWarp, TB>>>(xw_p, b2, g2, be2, af, af);

    k_mma<256><<<dim3(2, mBlocks), 256, SMEM>>>(af, w3t, xw_p, NN, 256);
    k_agg<3><<<gWarp, TB>>>(xw_p, b3, g3, be3, af, af);

    k_head<<<mBlocks, 256, SMEM>>>(af, wft, bf1, NN, Wf2, bf2, out);
}